// round 9
// baseline (speedup 1.0000x reference)
#include <cuda_runtime.h>
#include <cuda_bf16.h>
#include <cmath>

typedef __nv_bfloat16 bf16;

#define BATCH 2
#define SEQ   2048
#define DM    2048
#define NH    16
#define HD    128
#define MR    (BATCH*SEQ)
#define MD    ((size_t)MR*DM)
#define DD    ((size_t)DM*DM)
#define SM_SCALE 0.08838834764831845f

// ---------------- static device scratch ----------------
__device__ __align__(1024) bf16 g_Xh[MD], g_Xl[MD];
__device__ __align__(1024) bf16 g_Wh[4*DD], g_Wl[4*DD];
__device__ __align__(1024) bf16 g_Qh[MD], g_Ql[MD], g_Kh[MD], g_Kl[MD], g_Vh[MD], g_Vl[MD];
__device__ __align__(1024) float g_fQ[MD], g_fK[MD], g_fV[MD];
__device__ float g_cos[SEQ*64], g_sin[SEQ*64];

// ---------------- helpers ----------------
__device__ __forceinline__ unsigned sptr(const void* p) {
    return (unsigned)__cvta_generic_to_shared(p);
}
__device__ __forceinline__ void ldmx4(unsigned* r, unsigned a) {
    asm volatile("ldmatrix.sync.aligned.m8n8.x4.shared.b16 {%0,%1,%2,%3}, [%4];\n"
        : "=r"(r[0]), "=r"(r[1]), "=r"(r[2]), "=r"(r[3]) : "r"(a));
}
__device__ __forceinline__ void ldmx2(unsigned* r, unsigned a) {
    asm volatile("ldmatrix.sync.aligned.m8n8.x2.shared.b16 {%0,%1}, [%2];\n"
        : "=r"(r[0]), "=r"(r[1]) : "r"(a));
}
__device__ __forceinline__ void ldmx2t(unsigned* r, unsigned a) {
    asm volatile("ldmatrix.sync.aligned.m8n8.x2.trans.shared.b16 {%0,%1}, [%2];\n"
        : "=r"(r[0]), "=r"(r[1]) : "r"(a));
}
__device__ __forceinline__ void mma_bf16(float* c, const unsigned* a, const unsigned* b) {
    asm volatile("mma.sync.aligned.m16n8k16.row.col.f32.bf16.bf16.f32 "
        "{%0,%1,%2,%3}, {%4,%5,%6,%7}, {%8,%9}, {%0,%1,%2,%3};\n"
        : "+f"(c[0]), "+f"(c[1]), "+f"(c[2]), "+f"(c[3])
        : "r"(a[0]), "r"(a[1]), "r"(a[2]), "r"(a[3]), "r"(b[0]), "r"(b[1]));
}
__device__ __forceinline__ void cpa16(unsigned s, const void* g) {
    asm volatile("cp.async.cg.shared.global [%0], [%1], 16;\n" :: "r"(s), "l"(g));
}
__device__ __forceinline__ void split2(float x, float y, unsigned& hi, unsigned& lo) {
    bf16 hx = __float2bfloat16(x);
    bf16 hy = __float2bfloat16(y);
    bf16 lx = __float2bfloat16(x - __bfloat162float(hx));
    bf16 ly = __float2bfloat16(y - __bfloat162float(hy));
    hi = (unsigned)__bfloat16_as_ushort(hx) | ((unsigned)__bfloat16_as_ushort(hy) << 16);
    lo = (unsigned)__bfloat16_as_ushort(lx) | ((unsigned)__bfloat16_as_ushort(ly) << 16);
}
__device__ __forceinline__ void wr_hilo(bf16* H, bf16* L, size_t i, float x) {
    bf16 h = __float2bfloat16(x);
    H[i] = h;
    L[i] = __float2bfloat16(x - __bfloat162float(h));
}

// ---------------- fp32 -> bf16 hi/lo split ----------------
// sel: 0 = external src -> g_Xh/g_Xl ; 1 = external src -> g_Wh/g_Wl + off ;
//      2 = g_fQ (attention output) -> g_Xh/g_Xl
__global__ void split_kernel(const float* __restrict__ srcx, int sel, size_t off, int n4)
{
    int i = blockIdx.x * blockDim.x + threadIdx.x;
    if (i >= n4) return;
    const float* src = (sel == 2) ? (const float*)g_fQ : srcx;
    bf16* H = (sel == 1) ? g_Wh + off : g_Xh;
    bf16* L = (sel == 1) ? g_Wl + off : g_Xl;
    float4 v = ((const float4*)src)[i];
    unsigned h0, l0, h1, l1;
    split2(v.x, v.y, h0, l0);
    split2(v.z, v.w, h1, l1);
    ((uint2*)H)[i] = make_uint2(h0, h1);
    ((uint2*)L)[i] = make_uint2(l0, l1);
}

// ---------------- RoPE cos/sin table ----------------
__global__ void rope_table_kernel()
{
    int i = blockIdx.x * blockDim.x + threadIdx.x;
    if (i >= SEQ * 64) return;
    int j = i & 63, s = i >> 6;
    float invf = (float)exp(-(double)j * (9.210340371976184 / 64.0)); // 10000^(-j/64)
    float ang = (float)s * invf;   // mimic reference's fp32 t*inv_freq rounding
    g_cos[i] = (float)cos((double)ang);
    g_sin[i] = (float)sin((double)ang);
}

// ---------------- RoPE + relayout + split ----------------
// reads g_fQ/g_fK/g_fV ([B*S, D]) ; writes head-major [B,H,S,HD] bf16 hi/lo
__global__ void rope_kernel()
{
    size_t i = (size_t)blockIdx.x * blockDim.x + threadIdx.x;
    if (i >= (size_t)MR * NH * 64) return;
    int d  = (int)(i & 63);
    int h  = (int)((i >> 6) & 15);
    int bs = (int)(i >> 10);
    int s  = bs & (SEQ - 1);
    int b  = bs >> 11;
    size_t src = (size_t)bs * DM + (size_t)h * HD;
    float c  = g_cos[s * 64 + d], sn = g_sin[s * 64 + d];
    float q0 = g_fQ[src + d], q1 = g_fQ[src + d + 64];
    float k0 = g_fK[src + d], k1 = g_fK[src + d + 64];
    float v0 = g_fV[src + d], v1 = g_fV[src + d + 64];
    float qa = (q0 * c - q1 * sn) * SM_SCALE;
    float qb = (q1 * c + q0 * sn) * SM_SCALE;
    float ka = k0 * c - k1 * sn;
    float kb = k1 * c + k0 * sn;
    size_t dst = (((size_t)b * NH + h) * SEQ + s) * HD;
    wr_hilo(g_Qh, g_Ql, dst + d, qa);  wr_hilo(g_Qh, g_Ql, dst + d + 64, qb);
    wr_hilo(g_Kh, g_Kl, dst + d, ka);  wr_hilo(g_Kh, g_Kl, dst + d + 64, kb);
    wr_hilo(g_Vh, g_Vl, dst + d, v0);  wr_hilo(g_Vh, g_Vl, dst + d + 64, v1);
}

// ---------------- compensated bf16 GEMM: C[M,N] = A[M,K] * B[N,K]^T ----------------
#define GLD 40             // smem row stride (elements) for the 32-wide K tile
#define GTS (128*GLD)      // one tile (elements)

__device__ __forceinline__ void gemm_load(
    const bf16* Ah, const bf16* Al, const bf16* Bh, const bf16* Bl,
    bf16* s, int bm, int bn, int k0, int tid)
{
    #pragma unroll
    for (int c = tid; c < 512; c += 256) {
        int r = c >> 2, c8 = (c & 3) << 3;
        size_t ga = (size_t)(bm * 128 + r) * DM + k0 + c8;
        size_t gb = (size_t)(bn * 128 + r) * DM + k0 + c8;
        unsigned d = sptr(s + r * GLD + c8);
        cpa16(d,             Ah + ga);
        cpa16(d + 2*GTS,     Al + ga);   // +GTS elements = +2*GTS bytes
        cpa16(d + 4*GTS,     Bh + gb);
        cpa16(d + 6*GTS,     Bl + gb);
    }
    asm volatile("cp.async.commit_group;\n" ::);
}

__global__ void __launch_bounds__(256,1) gemm_kernel(float* extC, int w_idx, int c_sel)
{
    extern __shared__ bf16 smg[];
    const bf16* Ah = g_Xh;
    const bf16* Al = g_Xl;
    const bf16* Bh = g_Wh + (size_t)w_idx * DD;
    const bf16* Bl = g_Wl + (size_t)w_idx * DD;
    float* C = (c_sel == 0) ? g_fQ : (c_sel == 1) ? g_fK : (c_sel == 2) ? g_fV : extC;

    int tid = threadIdx.x, lane = tid & 31, wid = tid >> 5;
    int wm = wid & 1, wn = wid >> 1;
    int bm = blockIdx.y, bn = blockIdx.x;

    float acc[4][4][4];
    #pragma unroll
    for (int a = 0; a < 4; a++)
        #pragma unroll
        for (int b = 0; b < 4; b++)
            { acc[a][b][0]=0.f; acc[a][b][1]=0.f; acc[a][b][2]=0.f; acc[a][b][3]=0.f; }

    gemm_load(Ah, Al, Bh, Bl, smg, bm, bn, 0, tid);
    const int NK = DM / 32;
    for (int it = 0; it < NK; it++) {
        if (it + 1 < NK) {
            gemm_load(Ah, Al, Bh, Bl, smg + ((it + 1) & 1) * 4 * GTS, bm, bn, (it + 1) * 32, tid);
            asm volatile("cp.async.wait_group 1;\n" ::);
        } else {
            asm volatile("cp.async.wait_group 0;\n" ::);
        }
        __syncthreads();
        bf16* s   = smg + (it & 1) * 4 * GTS;
        bf16* sAh = s;
        bf16* sAl = s + GTS;
        bf16* sBh = s + 2 * GTS;
        bf16* sBl = s + 3 * GTS;
        #pragma unroll
        for (int k16 = 0; k16 < 2; k16++) {
            unsigned ah[4][4], al[4][4], bh[4][2], bl[4][2];
            int arow = wm * 64 + (lane & 15);
            int acol = k16 * 16 + ((lane >> 4) << 3);
            #pragma unroll
            for (int mf = 0; mf < 4; mf++) {
                ldmx4(ah[mf], sptr(sAh + (arow + mf * 16) * GLD + acol));
                ldmx4(al[mf], sptr(sAl + (arow + mf * 16) * GLD + acol));
            }
            int l8 = lane & 15;
            int brow = l8 & 7;
            int bcol = k16 * 16 + ((l8 >> 3) << 3);
            #pragma unroll
            for (int nf = 0; nf < 4; nf++) {
                int n0 = wn * 32 + nf * 8;
                ldmx2(bh[nf], sptr(sBh + (n0 + brow) * GLD + bcol));
                ldmx2(bl[nf], sptr(sBl + (n0 + brow) * GLD + bcol));
            }
            #pragma unroll
            for (int mf = 0; mf < 4; mf++)
                #pragma unroll
                for (int nf = 0; nf < 4; nf++) {
                    mma_bf16(acc[mf][nf], ah[mf], bh[nf]);
                    mma_bf16(acc[mf][nf], ah[mf], bl[nf]);
                    mma_bf16(acc[mf][nf], al[mf], bh[nf]);
                }
        }
        __syncthreads();
    }
    #pragma unroll
    for (int mf = 0; mf < 4; mf++)
        #pragma unroll
        for (int nf = 0; nf < 4; nf++) {
            int row = bm * 128 + wm * 64 + mf * 16 + (lane >> 2);
            int col = bn * 128 + wn * 32 + nf * 8 + ((lane & 3) << 1);
            *(float2*)(C + (size_t)row * DM + col)       = make_float2(acc[mf][nf][0], acc[mf][nf][1]);
            *(float2*)(C + (size_t)(row + 8) * DM + col) = make_float2(acc[mf][nf][2], acc[mf][nf][3]);
        }
}

// ---------------- flash attention (compensated) ----------------
#define ALD 136

__global__ void __launch_bounds__(256,1) attn_kernel()
{
    extern __shared__ bf16 sma[];
    bf16* sQh = sma;
    bf16* sQl = sQh + 128 * ALD;
    bf16* sKh = sQl + 128 * ALD;
    bf16* sKl = sKh + 64 * ALD;
    bf16* sVh = sKl + 64 * ALD;
    bf16* sVl = sVh + 64 * ALD;

    int tid = threadIdx.x, lane = tid & 31, w = tid >> 5;
    int qt = blockIdx.x, h = blockIdx.y, b = blockIdx.z;
    int qb = qt * 128;
    size_t base = (((size_t)b * NH + h) * SEQ) * HD;

    for (int c = tid; c < 2048; c += 256) {
        int r = c >> 4, c8 = (c & 15) << 3;
        size_t g = base + (size_t)(qb + r) * HD + c8;
        cpa16(sptr(sQh + r * ALD + c8), g_Qh + g);
        cpa16(sptr(sQl + r * ALD + c8), g_Ql + g);
    }
    asm volatile("cp.async.commit_group;\n" ::);

    float o[16][4];
    #pragma unroll
    for (int i = 0; i < 16; i++) { o[i][0]=0.f; o[i][1]=0.f; o[i][2]=0.f; o[i][3]=0.f; }
    float m0 = -1e30f, m1 = -1e30f, l0 = 0.f, l1 = 0.f;
    int nkv = 2 * qt + 2;

    for (int it = 0; it < nkv; it++) {
        int kb = it * 64;
        __syncthreads();
        for (int c = tid; c < 1024; c += 256) {
            int r = c >> 4, c8 = (c & 15) << 3;
            size_t g = base + (size_t)(kb + r) * HD + c8;
            cpa16(sptr(sKh + r * ALD + c8), g_Kh + g);
            cpa16(sptr(sKl + r * ALD + c8), g_Kl + g);
            cpa16(sptr(sVh + r * ALD + c8), g_Vh + g);
            cpa16(sptr(sVl + r * ALD + c8), g_Vl + g);
        }
        asm volatile("cp.async.commit_group;\n" ::);
        asm volatile("cp.async.wait_group 0;\n" ::);
        __syncthreads();

        // scores: S = Q K^T (compensated)
        float sc[8][4];
        #pragma unroll
        for (int i = 0; i < 8; i++) { sc[i][0]=0.f; sc[i][1]=0.f; sc[i][2]=0.f; sc[i][3]=0.f; }
        int arow = w * 16 + (lane & 15);
        int l8 = lane & 15, brow = l8 & 7, bc8 = (l8 >> 3) << 3;
        #pragma unroll
        for (int k16 = 0; k16 < 8; k16++) {
            unsigned ah[4], al[4];
            int acol = k16 * 16 + ((lane >> 4) << 3);
            ldmx4(ah, sptr(sQh + arow * ALD + acol));
            ldmx4(al, sptr(sQl + arow * ALD + acol));
            #pragma unroll
            for (int nf = 0; nf < 8; nf++) {
                unsigned bh[2], bl[2];
                ldmx2(bh, sptr(sKh + (nf * 8 + brow) * ALD + k16 * 16 + bc8));
                ldmx2(bl, sptr(sKl + (nf * 8 + brow) * ALD + k16 * 16 + bc8));
                mma_bf16(sc[nf], ah, bh);
                mma_bf16(sc[nf], ah, bl);
                mma_bf16(sc[nf], al, bh);
            }
        }
        // causal mask (only the last 2 kv tiles straddle the diagonal)
        int qr0 = qb + w * 16 + (lane >> 2);
        if (it >= nkv - 2) {
            #pragma unroll
            for (int nf = 0; nf < 8; nf++) {
                int col = kb + nf * 8 + ((lane & 3) << 1);
                if (col     > qr0)     sc[nf][0] = -1e30f;
                if (col + 1 > qr0)     sc[nf][1] = -1e30f;
                if (col     > qr0 + 8) sc[nf][2] = -1e30f;
                if (col + 1 > qr0 + 8) sc[nf][3] = -1e30f;
            }
        }
        // online softmax
        float mx0 = -1e30f, mx1 = -1e30f;
        #pragma unroll
        for (int nf = 0; nf < 8; nf++) {
            mx0 = fmaxf(mx0, fmaxf(sc[nf][0], sc[nf][1]));
            mx1 = fmaxf(mx1, fmaxf(sc[nf][2], sc[nf][3]));
        }
        mx0 = fmaxf(mx0, __shfl_xor_sync(0xffffffffu, mx0, 1));
        mx0 = fmaxf(mx0, __shfl_xor_sync(0xffffffffu, mx0, 2));
        mx1 = fmaxf(mx1, __shfl_xor_sync(0xffffffffu, mx1, 1));
        mx1 = fmaxf(mx1, __shfl_xor_sync(0xffffffffu, mx1, 2));
        float mn0 = fmaxf(m0, mx0), mn1 = fmaxf(m1, mx1);
        float a0 = __expf(m0 - mn0), a1 = __expf(m1 - mn1);
        float s0 = 0.f, s1 = 0.f;
        #pragma unroll
        for (int nf = 0; nf < 8; nf++) {
            sc[nf][0] = __expf(sc[nf][0] - mn0);
            sc[nf][1] = __expf(sc[nf][1] - mn0);
            sc[nf][2] = __expf(sc[nf][2] - mn1);
            sc[nf][3] = __expf(sc[nf][3] - mn1);
            s0 += sc[nf][0] + sc[nf][1];
            s1 += sc[nf][2] + sc[nf][3];
        }
        s0 += __shfl_xor_sync(0xffffffffu, s0, 1);
        s0 += __shfl_xor_sync(0xffffffffu, s0, 2);
        s1 += __shfl_xor_sync(0xffffffffu, s1, 1);
        s1 += __shfl_xor_sync(0xffffffffu, s1, 2);
        l0 = a0 * l0 + s0;
        l1 = a1 * l1 + s1;
        m0 = mn0; m1 = mn1;
        #pragma unroll
        for (int i = 0; i < 16; i++) { o[i][0]*=a0; o[i][1]*=a0; o[i][2]*=a1; o[i][3]*=a1; }

        // PV (compensated): P C-frags become A-frags directly
        #pragma unroll
        for (int k16 = 0; k16 < 4; k16++) {
            unsigned ph[4], pl[4];
            split2(sc[2*k16][0],   sc[2*k16][1],   ph[0], pl[0]);
            split2(sc[2*k16][2],   sc[2*k16][3],   ph[1], pl[1]);
            split2(sc[2*k16+1][0], sc[2*k16+1][1], ph[2], pl[2]);
            split2(sc[2*k16+1][2], sc[2*k16+1][3], ph[3], pl[3]);
            #pragma unroll
            for (int nf = 0; nf < 16; nf++) {
                unsigned vh[2], vl[2];
                ldmx2t(vh, sptr(sVh + (k16 * 16 + l8) * ALD + nf * 8));
                ldmx2t(vl, sptr(sVl + (k16 * 16 + l8) * ALD + nf * 8));
                mma_bf16(o[nf], ph, vh);
                mma_bf16(o[nf], ph, vl);
                mma_bf16(o[nf], pl, vh);
            }
        }
    }
    // epilogue: O /= l, write fp32 AO (reuses g_fQ) in [B,S,H*HD] layout
    float r0 = 1.f / l0, r1 = 1.f / l1;
    int srow = qb + w * 16 + (lane >> 2);
    #pragma unroll
    for (int nf = 0; nf < 16; nf++) {
        int col = nf * 8 + ((lane & 3) << 1);
        size_t p0 = (((size_t)b * SEQ + srow) * NH + h) * HD + col;
        size_t p1 = (((size_t)b * SEQ + srow + 8) * NH + h) * HD + col;
        *(float2*)(g_fQ + p0) = make_float2(o[nf][0] * r0, o[nf][1] * r0);
        *(float2*)(g_fQ + p1) = make_float2(o[nf][2] * r1, o[nf][3] * r1);
    }
}

// ---------------- launch ----------------
extern "C" void kernel_launch(void* const* d_in, const int* in_sizes, int n_in,
                              void* d_out, int out_size)
{
    const float* X = (const float*)d_in[0];
    float* out = (float*)d_out;

    size_t gemm_smem = (size_t)8 * GTS * sizeof(bf16);                 // 81920 B
    size_t attn_smem = (size_t)(2 * 128 + 4 * 64) * ALD * sizeof(bf16); // 139264 B
    cudaFuncSetAttribute(gemm_kernel, cudaFuncAttributeMaxDynamicSharedMemorySize, (int)gemm_smem);
    cudaFuncSetAttribute(attn_kernel, cudaFuncAttributeMaxDynamicSharedMemorySize, (int)attn_smem);

    int n4x = (int)(MD / 4);
    split_kernel<<<(n4x + 255) / 256, 256>>>(X, 0, 0, n4x);
    int n4w = (int)(DD / 4);
    for (int i = 0; i < 4; i++)
        split_kernel<<<(n4w + 255) / 256, 256>>>((const float*)d_in[1 + i], 1, (size_t)i * DD, n4w);
    rope_table_kernel<<<(SEQ * 64) / 256, 256>>>();

    dim3 gg(DM / 128, MR / 128);
    gemm_kernel<<<gg, 256, gemm_smem>>>(out, 0, 0);   // Q
    gemm_kernel<<<gg, 256, gemm_smem>>>(out, 1, 1);   // K
    gemm_kernel<<<gg, 256, gemm_smem>>>(out, 2, 2);   // V

    rope_kernel<<<(int)(((size_t)MR * NH * 64) / 256), 256>>>();

    attn_kernel<<<dim3(SEQ / 128, NH, BATCH), 256, attn_smem>>>();

    split_kernel<<<(n4x + 255) / 256, 256>>>(X, 2, 0, n4x);  // AO -> hi/lo
    gemm_kernel<<<gg, 256, gemm_smem>>>(out, 3, 3);          // out = AO @ Wo^T
}

// round 10
// speedup vs baseline: 1.0014x; 1.0014x over previous
#include <cuda_runtime.h>
#include <cuda_bf16.h>
#include <cmath>

typedef __nv_bfloat16 bf16;

#define BATCH 2
#define SEQ   2048
#define DM    2048
#define NH    16
#define HD    128
#define MR    (BATCH*SEQ)
#define MD    ((size_t)MR*DM)
#define DD    ((size_t)DM*DM)
#define SM_SCALE 0.08838834764831845f

// ---------------- static device scratch ----------------
__device__ __align__(1024) bf16 g_Xh[MD], g_Xl[MD];
__device__ __align__(1024) bf16 g_Wh[4*DD], g_Wl[4*DD];
__device__ __align__(1024) bf16 g_Qh[MD], g_Ql[MD], g_Kh[MD], g_Kl[MD], g_Vh[MD], g_Vl[MD];
__device__ __align__(1024) float g_fQ[MD], g_fK[MD], g_fV[MD];
__device__ float g_cos[SEQ*64], g_sin[SEQ*64];

// ---------------- helpers ----------------
__device__ __forceinline__ unsigned sptr(const void* p) {
    return (unsigned)__cvta_generic_to_shared(p);
}
__device__ __forceinline__ void ldmx4(unsigned* r, unsigned a) {
    asm volatile("ldmatrix.sync.aligned.m8n8.x4.shared.b16 {%0,%1,%2,%3}, [%4];\n"
        : "=r"(r[0]), "=r"(r[1]), "=r"(r[2]), "=r"(r[3]) : "r"(a));
}
__device__ __forceinline__ void ldmx2(unsigned* r, unsigned a) {
    asm volatile("ldmatrix.sync.aligned.m8n8.x2.shared.b16 {%0,%1}, [%2];\n"
        : "=r"(r[0]), "=r"(r[1]) : "r"(a));
}
__device__ __forceinline__ void ldmx2t(unsigned* r, unsigned a) {
    asm volatile("ldmatrix.sync.aligned.m8n8.x2.trans.shared.b16 {%0,%1}, [%2];\n"
        : "=r"(r[0]), "=r"(r[1]) : "r"(a));
}
__device__ __forceinline__ void mma_bf16(float* c, const unsigned* a, const unsigned* b) {
    asm volatile("mma.sync.aligned.m16n8k16.row.col.f32.bf16.bf16.f32 "
        "{%0,%1,%2,%3}, {%4,%5,%6,%7}, {%8,%9}, {%0,%1,%2,%3};\n"
        : "+f"(c[0]), "+f"(c[1]), "+f"(c[2]), "+f"(c[3])
        : "r"(a[0]), "r"(a[1]), "r"(a[2]), "r"(a[3]), "r"(b[0]), "r"(b[1]));
}
__device__ __forceinline__ void cpa16(unsigned s, const void* g) {
    asm volatile("cp.async.cg.shared.global [%0], [%1], 16;\n" :: "r"(s), "l"(g));
}
__device__ __forceinline__ void split2(float x, float y, unsigned& hi, unsigned& lo) {
    bf16 hx = __float2bfloat16(x);
    bf16 hy = __float2bfloat16(y);
    bf16 lx = __float2bfloat16(x - __bfloat162float(hx));
    bf16 ly = __float2bfloat16(y - __bfloat162float(hy));
    hi = (unsigned)__bfloat16_as_ushort(hx) | ((unsigned)__bfloat16_as_ushort(hy) << 16);
    lo = (unsigned)__bfloat16_as_ushort(lx) | ((unsigned)__bfloat16_as_ushort(ly) << 16);
}
__device__ __forceinline__ void wr_hilo(bf16* H, bf16* L, size_t i, float x) {
    bf16 h = __float2bfloat16(x);
    H[i] = h;
    L[i] = __float2bfloat16(x - __bfloat162float(h));
}

// ---------------- fp32 -> bf16 hi/lo split ----------------
// sel: 0 = external src -> g_Xh/g_Xl ; 1 = external src -> g_Wh/g_Wl + off ;
//      2 = g_fQ (attention output) -> g_Xh/g_Xl
__global__ void split_kernel(const float* __restrict__ srcx, int sel, size_t off, int n4)
{
    int i = blockIdx.x * blockDim.x + threadIdx.x;
    if (i >= n4) return;
    const float* src = (sel == 2) ? (const float*)g_fQ : srcx;
    bf16* H = (sel == 1) ? g_Wh + off : g_Xh;
    bf16* L = (sel == 1) ? g_Wl + off : g_Xl;
    float4 v = ((const float4*)src)[i];
    unsigned h0, l0, h1, l1;
    split2(v.x, v.y, h0, l0);
    split2(v.z, v.w, h1, l1);
    ((uint2*)H)[i] = make_uint2(h0, h1);
    ((uint2*)L)[i] = make_uint2(l0, l1);
}

// ---------------- RoPE cos/sin table ----------------
__global__ void rope_table_kernel()
{
    int i = blockIdx.x * blockDim.x + threadIdx.x;
    if (i >= SEQ * 64) return;
    int j = i & 63, s = i >> 6;
    float invf = (float)exp(-(double)j * (9.210340371976184 / 64.0)); // 10000^(-j/64)
    float ang = (float)s * invf;   // mimic reference's fp32 t*inv_freq rounding
    g_cos[i] = (float)cos((double)ang);
    g_sin[i] = (float)sin((double)ang);
}

// ---------------- RoPE + relayout + split ----------------
// reads g_fQ/g_fK/g_fV ([B*S, D]) ; writes head-major [B,H,S,HD] bf16 hi/lo
__global__ void rope_kernel()
{
    size_t i = (size_t)blockIdx.x * blockDim.x + threadIdx.x;
    if (i >= (size_t)MR * NH * 64) return;
    int d  = (int)(i & 63);
    int h  = (int)((i >> 6) & 15);
    int bs = (int)(i >> 10);
    int s  = bs & (SEQ - 1);
    int b  = bs >> 11;
    size_t src = (size_t)bs * DM + (size_t)h * HD;
    float c  = g_cos[s * 64 + d], sn = g_sin[s * 64 + d];
    float q0 = g_fQ[src + d], q1 = g_fQ[src + d + 64];
    float k0 = g_fK[src + d], k1 = g_fK[src + d + 64];
    float v0 = g_fV[src + d], v1 = g_fV[src + d + 64];
    float qa = (q0 * c - q1 * sn) * SM_SCALE;
    float qb = (q1 * c + q0 * sn) * SM_SCALE;
    float ka = k0 * c - k1 * sn;
    float kb = k1 * c + k0 * sn;
    size_t dst = (((size_t)b * NH + h) * SEQ + s) * HD;
    wr_hilo(g_Qh, g_Ql, dst + d, qa);  wr_hilo(g_Qh, g_Ql, dst + d + 64, qb);
    wr_hilo(g_Kh, g_Kl, dst + d, ka);  wr_hilo(g_Kh, g_Kl, dst + d + 64, kb);
    wr_hilo(g_Vh, g_Vl, dst + d, v0);  wr_hilo(g_Vh, g_Vl, dst + d + 64, v1);
}

// ---------------- compensated bf16 GEMM: C[M,N] = A[M,K] * B[N,K]^T ----------------
#define GLD 40             // smem row stride (elements) for the 32-wide K tile
#define GTS (128*GLD)      // one tile (elements)

__device__ __forceinline__ void gemm_load(
    const bf16* Ah, const bf16* Al, const bf16* Bh, const bf16* Bl,
    bf16* s, int bm, int bn, int k0, int tid)
{
    #pragma unroll
    for (int c = tid; c < 512; c += 256) {
        int r = c >> 2, c8 = (c & 3) << 3;
        size_t ga = (size_t)(bm * 128 + r) * DM + k0 + c8;
        size_t gb = (size_t)(bn * 128 + r) * DM + k0 + c8;
        unsigned d = sptr(s + r * GLD + c8);
        cpa16(d,             Ah + ga);
        cpa16(d + 2*GTS,     Al + ga);   // +GTS elements = +2*GTS bytes
        cpa16(d + 4*GTS,     Bh + gb);
        cpa16(d + 6*GTS,     Bl + gb);
    }
    asm volatile("cp.async.commit_group;\n" ::);
}

__global__ void __launch_bounds__(256,1) gemm_kernel(float* extC, int w_idx, int c_sel)
{
    extern __shared__ bf16 smg[];
    const bf16* Ah = g_Xh;
    const bf16* Al = g_Xl;
    const bf16* Bh = g_Wh + (size_t)w_idx * DD;
    const bf16* Bl = g_Wl + (size_t)w_idx * DD;
    float* C = (c_sel == 0) ? g_fQ : (c_sel == 1) ? g_fK : (c_sel == 2) ? g_fV : extC;

    int tid = threadIdx.x, lane = tid & 31, wid = tid >> 5;
    int wm = wid & 1, wn = wid >> 1;
    int bm = blockIdx.y, bn = blockIdx.x;

    float acc[4][4][4];
    #pragma unroll
    for (int a = 0; a < 4; a++)
        #pragma unroll
        for (int b = 0; b < 4; b++)
            { acc[a][b][0]=0.f; acc[a][b][1]=0.f; acc[a][b][2]=0.f; acc[a][b][3]=0.f; }

    gemm_load(Ah, Al, Bh, Bl, smg, bm, bn, 0, tid);
    const int NK = DM / 32;
    for (int it = 0; it < NK; it++) {
        if (it + 1 < NK) {
            gemm_load(Ah, Al, Bh, Bl, smg + ((it + 1) & 1) * 4 * GTS, bm, bn, (it + 1) * 32, tid);
            asm volatile("cp.async.wait_group 1;\n" ::);
        } else {
            asm volatile("cp.async.wait_group 0;\n" ::);
        }
        __syncthreads();
        bf16* s   = smg + (it & 1) * 4 * GTS;
        bf16* sAh = s;
        bf16* sAl = s + GTS;
        bf16* sBh = s + 2 * GTS;
        bf16* sBl = s + 3 * GTS;
        #pragma unroll
        for (int k16 = 0; k16 < 2; k16++) {
            unsigned ah[4][4], al[4][4], bh[4][2], bl[4][2];
            int arow = wm * 64 + (lane & 15);
            int acol = k16 * 16 + ((lane >> 4) << 3);
            #pragma unroll
            for (int mf = 0; mf < 4; mf++) {
                ldmx4(ah[mf], sptr(sAh + (arow + mf * 16) * GLD + acol));
                ldmx4(al[mf], sptr(sAl + (arow + mf * 16) * GLD + acol));
            }
            int l8 = lane & 15;
            int brow = l8 & 7;
            int bcol = k16 * 16 + ((l8 >> 3) << 3);
            #pragma unroll
            for (int nf = 0; nf < 4; nf++) {
                int n0 = wn * 32 + nf * 8;
                ldmx2(bh[nf], sptr(sBh + (n0 + brow) * GLD + bcol));
                ldmx2(bl[nf], sptr(sBl + (n0 + brow) * GLD + bcol));
            }
            #pragma unroll
            for (int mf = 0; mf < 4; mf++)
                #pragma unroll
                for (int nf = 0; nf < 4; nf++) {
                    mma_bf16(acc[mf][nf], ah[mf], bh[nf]);
                    mma_bf16(acc[mf][nf], ah[mf], bl[nf]);
                    mma_bf16(acc[mf][nf], al[mf], bh[nf]);
                }
        }
        __syncthreads();
    }
    #pragma unroll
    for (int mf = 0; mf < 4; mf++)
        #pragma unroll
        for (int nf = 0; nf < 4; nf++) {
            int row = bm * 128 + wm * 64 + mf * 16 + (lane >> 2);
            int col = bn * 128 + wn * 32 + nf * 8 + ((lane & 3) << 1);
            *(float2*)(C + (size_t)row * DM + col)       = make_float2(acc[mf][nf][0], acc[mf][nf][1]);
            *(float2*)(C + (size_t)(row + 8) * DM + col) = make_float2(acc[mf][nf][2], acc[mf][nf][3]);
        }
}

// ---------------- flash attention (compensated) ----------------
#define ALD 136

__global__ void __launch_bounds__(256,1) attn_kernel()
{
    extern __shared__ bf16 sma[];
    bf16* sQh = sma;
    bf16* sQl = sQh + 128 * ALD;
    bf16* sKh = sQl + 128 * ALD;
    bf16* sKl = sKh + 64 * ALD;
    bf16* sVh = sKl + 64 * ALD;
    bf16* sVl = sVh + 64 * ALD;

    int tid = threadIdx.x, lane = tid & 31, w = tid >> 5;
    int qt = blockIdx.x, h = blockIdx.y, b = blockIdx.z;
    int qb = qt * 128;
    size_t base = (((size_t)b * NH + h) * SEQ) * HD;

    for (int c = tid; c < 2048; c += 256) {
        int r = c >> 4, c8 = (c & 15) << 3;
        size_t g = base + (size_t)(qb + r) * HD + c8;
        cpa16(sptr(sQh + r * ALD + c8), g_Qh + g);
        cpa16(sptr(sQl + r * ALD + c8), g_Ql + g);
    }
    asm volatile("cp.async.commit_group;\n" ::);

    float o[16][4];
    #pragma unroll
    for (int i = 0; i < 16; i++) { o[i][0]=0.f; o[i][1]=0.f; o[i][2]=0.f; o[i][3]=0.f; }
    float m0 = -1e30f, m1 = -1e30f, l0 = 0.f, l1 = 0.f;
    int nkv = 2 * qt + 2;

    for (int it = 0; it < nkv; it++) {
        int kb = it * 64;
        __syncthreads();
        for (int c = tid; c < 1024; c += 256) {
            int r = c >> 4, c8 = (c & 15) << 3;
            size_t g = base + (size_t)(kb + r) * HD + c8;
            cpa16(sptr(sKh + r * ALD + c8), g_Kh + g);
            cpa16(sptr(sKl + r * ALD + c8), g_Kl + g);
            cpa16(sptr(sVh + r * ALD + c8), g_Vh + g);
            cpa16(sptr(sVl + r * ALD + c8), g_Vl + g);
        }
        asm volatile("cp.async.commit_group;\n" ::);
        asm volatile("cp.async.wait_group 0;\n" ::);
        __syncthreads();

        // scores: S = Q K^T (compensated)
        float sc[8][4];
        #pragma unroll
        for (int i = 0; i < 8; i++) { sc[i][0]=0.f; sc[i][1]=0.f; sc[i][2]=0.f; sc[i][3]=0.f; }
        int arow = w * 16 + (lane & 15);
        int l8 = lane & 15, brow = l8 & 7, bc8 = (l8 >> 3) << 3;
        #pragma unroll
        for (int k16 = 0; k16 < 8; k16++) {
            unsigned ah[4], al[4];
            int acol = k16 * 16 + ((lane >> 4) << 3);
            ldmx4(ah, sptr(sQh + arow * ALD + acol));
            ldmx4(al, sptr(sQl + arow * ALD + acol));
            #pragma unroll
            for (int nf = 0; nf < 8; nf++) {
                unsigned bh[2], bl[2];
                ldmx2(bh, sptr(sKh + (nf * 8 + brow) * ALD + k16 * 16 + bc8));
                ldmx2(bl, sptr(sKl + (nf * 8 + brow) * ALD + k16 * 16 + bc8));
                mma_bf16(sc[nf], ah, bh);
                mma_bf16(sc[nf], ah, bl);
                mma_bf16(sc[nf], al, bh);
            }
        }
        // causal mask (only the last 2 kv tiles straddle the diagonal)
        int qr0 = qb + w * 16 + (lane >> 2);
        if (it >= nkv - 2) {
            #pragma unroll
            for (int nf = 0; nf < 8; nf++) {
                int col = kb + nf * 8 + ((lane & 3) << 1);
                if (col     > qr0)     sc[nf][0] = -1e30f;
                if (col + 1 > qr0)     sc[nf][1] = -1e30f;
                if (col     > qr0 + 8) sc[nf][2] = -1e30f;
                if (col + 1 > qr0 + 8) sc[nf][3] = -1e30f;
            }
        }
        // online softmax
        float mx0 = -1e30f, mx1 = -1e30f;
        #pragma unroll
        for (int nf = 0; nf < 8; nf++) {
            mx0 = fmaxf(mx0, fmaxf(sc[nf][0], sc[nf][1]));
            mx1 = fmaxf(mx1, fmaxf(sc[nf][2], sc[nf][3]));
        }
        mx0 = fmaxf(mx0, __shfl_xor_sync(0xffffffffu, mx0, 1));
        mx0 = fmaxf(mx0, __shfl_xor_sync(0xffffffffu, mx0, 2));
        mx1 = fmaxf(mx1, __shfl_xor_sync(0xffffffffu, mx1, 1));
        mx1 = fmaxf(mx1, __shfl_xor_sync(0xffffffffu, mx1, 2));
        float mn0 = fmaxf(m0, mx0), mn1 = fmaxf(m1, mx1);
        float a0 = __expf(m0 - mn0), a1 = __expf(m1 - mn1);
        float s0 = 0.f, s1 = 0.f;
        #pragma unroll
        for (int nf = 0; nf < 8; nf++) {
            sc[nf][0] = __expf(sc[nf][0] - mn0);
            sc[nf][1] = __expf(sc[nf][1] - mn0);
            sc[nf][2] = __expf(sc[nf][2] - mn1);
            sc[nf][3] = __expf(sc[nf][3] - mn1);
            s0 += sc[nf][0] + sc[nf][1];
            s1 += sc[nf][2] + sc[nf][3];
        }
        s0 += __shfl_xor_sync(0xffffffffu, s0, 1);
        s0 += __shfl_xor_sync(0xffffffffu, s0, 2);
        s1 += __shfl_xor_sync(0xffffffffu, s1, 1);
        s1 += __shfl_xor_sync(0xffffffffu, s1, 2);
        l0 = a0 * l0 + s0;
        l1 = a1 * l1 + s1;
        m0 = mn0; m1 = mn1;
        #pragma unroll
        for (int i = 0; i < 16; i++) { o[i][0]*=a0; o[i][1]*=a0; o[i][2]*=a1; o[i][3]*=a1; }

        // PV (compensated): P C-frags become A-frags directly
        #pragma unroll
        for (int k16 = 0; k16 < 4; k16++) {
            unsigned ph[4], pl[4];
            split2(sc[2*k16][0],   sc[2*k16][1],   ph[0], pl[0]);
            split2(sc[2*k16][2],   sc[2*k16][3],   ph[1], pl[1]);
            split2(sc[2*k16+1][0], sc[2*k16+1][1], ph[2], pl[2]);
            split2(sc[2*k16+1][2], sc[2*k16+1][3], ph[3], pl[3]);
            #pragma unroll
            for (int nf = 0; nf < 16; nf++) {
                unsigned vh[2], vl[2];
                ldmx2t(vh, sptr(sVh + (k16 * 16 + l8) * ALD + nf * 8));
                ldmx2t(vl, sptr(sVl + (k16 * 16 + l8) * ALD + nf * 8));
                mma_bf16(o[nf], ph, vh);
                mma_bf16(o[nf], ph, vl);
                mma_bf16(o[nf], pl, vh);
            }
        }
    }
    // epilogue: O /= l, write fp32 AO (reuses g_fQ) in [B,S,H*HD] layout
    float r0 = 1.f / l0, r1 = 1.f / l1;
    int srow = qb + w * 16 + (lane >> 2);
    #pragma unroll
    for (int nf = 0; nf < 16; nf++) {
        int col = nf * 8 + ((lane & 3) << 1);
        size_t p0 = (((size_t)b * SEQ + srow) * NH + h) * HD + col;
        size_t p1 = (((size_t)b * SEQ + srow + 8) * NH + h) * HD + col;
        *(float2*)(g_fQ + p0) = make_float2(o[nf][0] * r0, o[nf][1] * r0);
        *(float2*)(g_fQ + p1) = make_float2(o[nf][2] * r1, o[nf][3] * r1);
    }
}

// ---------------- launch ----------------
extern "C" void kernel_launch(void* const* d_in, const int* in_sizes, int n_in,
                              void* d_out, int out_size)
{
    const float* X = (const float*)d_in[0];
    float* out = (float*)d_out;

    size_t gemm_smem = (size_t)8 * GTS * sizeof(bf16);                 // 81920 B
    size_t attn_smem = (size_t)(2 * 128 + 4 * 64) * ALD * sizeof(bf16); // 139264 B
    cudaFuncSetAttribute(gemm_kernel, cudaFuncAttributeMaxDynamicSharedMemorySize, (int)gemm_smem);
    cudaFuncSetAttribute(attn_kernel, cudaFuncAttributeMaxDynamicSharedMemorySize, (int)attn_smem);

    int n4x = (int)(MD / 4);
    split_kernel<<<(n4x + 255) / 256, 256>>>(X, 0, 0, n4x);
    int n4w = (int)(DD / 4);
    for (int i = 0; i < 4; i++)
        split_kernel<<<(n4w + 255) / 256, 256>>>((const float*)d_in[1 + i], 1, (size_t)i * DD, n4w);
    rope_table_kernel<<<(SEQ * 64) / 256, 256>>>();

    dim3 gg(DM / 128, MR / 128);
    gemm_kernel<<<gg, 256, gemm_smem>>>(out, 0, 0);   // Q
    gemm_kernel<<<gg, 256, gemm_smem>>>(out, 1, 1);   // K
    gemm_kernel<<<gg, 256, gemm_smem>>>(out, 2, 2);   // V

    rope_kernel<<<(int)(((size_t)MR * NH * 64) / 256), 256>>>();

    attn_kernel<<<dim3(SEQ / 128, NH, BATCH), 256, attn_smem>>>();

    split_kernel<<<(n4x + 255) / 256, 256>>>(X, 2, 0, n4x);  // AO -> hi/lo
    gemm_kernel<<<gg, 256, gemm_smem>>>(out, 3, 3);          // out = AO @ Wo^T
}

// round 12
// speedup vs baseline: 1.1866x; 1.1850x over previous
#include <cuda_runtime.h>
#include <cuda_bf16.h>
#include <cmath>

typedef __nv_bfloat16 bf16;

#define BATCH 2
#define SEQ   2048
#define DM    2048
#define NH    16
#define HD    128
#define MR    (BATCH*SEQ)
#define MD    ((size_t)MR*DM)
#define DD    ((size_t)DM*DM)
#define SM_SCALE 0.08838834764831845f

// ---------------- static device scratch ----------------
__device__ __align__(1024) bf16 g_Xh[MD], g_Xl[MD];
__device__ __align__(1024) bf16 g_Wh[4*DD], g_Wl[4*DD];
__device__ __align__(1024) bf16 g_Qh[MD], g_Ql[MD], g_Kh[MD], g_Kl[MD], g_Vh[MD], g_Vl[MD];
__device__ float g_cos[SEQ*64], g_sin[SEQ*64];

// ---------------- helpers ----------------
__device__ __forceinline__ unsigned sptr(const void* p) {
    return (unsigned)__cvta_generic_to_shared(p);
}
__device__ __forceinline__ void ldmx4(unsigned* r, unsigned a) {
    asm volatile("ldmatrix.sync.aligned.m8n8.x4.shared.b16 {%0,%1,%2,%3}, [%4];\n"
        : "=r"(r[0]), "=r"(r[1]), "=r"(r[2]), "=r"(r[3]) : "r"(a));
}
__device__ __forceinline__ void ldmx2(unsigned* r, unsigned a) {
    asm volatile("ldmatrix.sync.aligned.m8n8.x2.shared.b16 {%0,%1}, [%2];\n"
        : "=r"(r[0]), "=r"(r[1]) : "r"(a));
}
__device__ __forceinline__ void ldmx2t(unsigned* r, unsigned a) {
    asm volatile("ldmatrix.sync.aligned.m8n8.x2.trans.shared.b16 {%0,%1}, [%2];\n"
        : "=r"(r[0]), "=r"(r[1]) : "r"(a));
}
__device__ __forceinline__ void mma_bf16(float* c, const unsigned* a, const unsigned* b) {
    asm volatile("mma.sync.aligned.m16n8k16.row.col.f32.bf16.bf16.f32 "
        "{%0,%1,%2,%3}, {%4,%5,%6,%7}, {%8,%9}, {%0,%1,%2,%3};\n"
        : "+f"(c[0]), "+f"(c[1]), "+f"(c[2]), "+f"(c[3])
        : "r"(a[0]), "r"(a[1]), "r"(a[2]), "r"(a[3]), "r"(b[0]), "r"(b[1]));
}
__device__ __forceinline__ void cpa16(unsigned s, const void* g) {
    asm volatile("cp.async.cg.shared.global [%0], [%1], 16;\n" :: "r"(s), "l"(g));
}
__device__ __forceinline__ void split2(float x, float y, unsigned& hi, unsigned& lo) {
    bf16 hx = __float2bfloat16(x);
    bf16 hy = __float2bfloat16(y);
    bf16 lx = __float2bfloat16(x - __bfloat162float(hx));
    bf16 ly = __float2bfloat16(y - __bfloat162float(hy));
    hi = (unsigned)__bfloat16_as_ushort(hx) | ((unsigned)__bfloat16_as_ushort(hy) << 16);
    lo = (unsigned)__bfloat16_as_ushort(lx) | ((unsigned)__bfloat16_as_ushort(ly) << 16);
}
__device__ __forceinline__ void wr_hilo(bf16* H, bf16* L, size_t i, float x) {
    bf16 h = __float2bfloat16(x);
    H[i] = h;
    L[i] = __float2bfloat16(x - __bfloat162float(h));
}

// ---------------- fp32 -> bf16 hi/lo split ----------------
__global__ void split_kernel(const float* __restrict__ src, int sel, size_t off, int n4)
{
    int i = blockIdx.x * blockDim.x + threadIdx.x;
    if (i >= n4) return;
    bf16* H = (sel == 1) ? g_Wh + off : g_Xh;
    bf16* L = (sel == 1) ? g_Wl + off : g_Xl;
    float4 v = ((const float4*)src)[i];
    unsigned h0, l0, h1, l1;
    split2(v.x, v.y, h0, l0);
    split2(v.z, v.w, h1, l1);
    ((uint2*)H)[i] = make_uint2(h0, h1);
    ((uint2*)L)[i] = make_uint2(l0, l1);
}

// ---------------- RoPE cos/sin table ----------------
__global__ void rope_table_kernel()
{
    int i = blockIdx.x * blockDim.x + threadIdx.x;
    if (i >= SEQ * 64) return;
    int j = i & 63, s = i >> 6;
    float invf = (float)exp(-(double)j * (9.210340371976184 / 64.0)); // 10000^(-j/64)
    float ang = (float)s * invf;   // mimic reference's fp32 t*inv_freq rounding
    g_cos[i] = (float)cos((double)ang);
    g_sin[i] = (float)sin((double)ang);
}

// ======== compensated bf16 GEMM: C[M,N] = A[M,K] * B[N,K]^T (legacy mma) ========
// tile 128x128, K-chunk 32, double-buffered cp.async, occupancy 2.
// mode 0: fused QKV (grid x = 48; w = bn>>4) with RoPE+split epilogue
// mode 1: output projection (grid x = 16; w = 3), fp32 epilogue to extC
#define GLD 40             // smem row stride (elements) for the 32-wide K chunk
#define GTS (128*GLD)      // one operand quadrant (elements)
#define GSMEM ((size_t)8*GTS*sizeof(bf16))   // 81920 B (2 stages x 4 quadrants)

__device__ __forceinline__ void gemm_load(
    const bf16* Ah, const bf16* Al, const bf16* Bh, const bf16* Bl,
    bf16* s, int arow0, int brow0, int k0, int tid)
{
    #pragma unroll
    for (int c = tid; c < 512; c += 256) {
        int r = c >> 2, c8 = (c & 3) << 3;
        size_t ga = (size_t)(arow0 + r) * DM + k0 + c8;
        size_t gb = (size_t)(brow0 + r) * DM + k0 + c8;
        unsigned d = sptr(s + r * GLD + c8);
        cpa16(d,           Ah + ga);
        cpa16(d + 2*GTS,   Al + ga);   // quadrant offsets in BYTES (elem*2)
        cpa16(d + 4*GTS,   Bh + gb);
        cpa16(d + 6*GTS,   Bl + gb);
    }
    asm volatile("cp.async.commit_group;\n" ::);
}

__global__ void __launch_bounds__(256,2) gemm_kernel(float* extC, int mode)
{
    extern __shared__ bf16 smg[];
    int tid = threadIdx.x, lane = tid & 31, wid = tid >> 5;
    int wm = wid & 1, wn = wid >> 1;
    int bm = blockIdx.y, bn = blockIdx.x;

    int w_idx = mode ? 3 : (bn >> 4);
    int bcol0 = mode ? bn * 128 : (bn & 15) * 128;
    const bf16* Ah = g_Xh;
    const bf16* Al = g_Xl;
    const bf16* Bh = g_Wh + (size_t)w_idx * DD;
    const bf16* Bl = g_Wl + (size_t)w_idx * DD;

    float acc[4][4][4];
    #pragma unroll
    for (int a = 0; a < 4; a++)
        #pragma unroll
        for (int b = 0; b < 4; b++)
            { acc[a][b][0]=0.f; acc[a][b][1]=0.f; acc[a][b][2]=0.f; acc[a][b][3]=0.f; }

    gemm_load(Ah, Al, Bh, Bl, smg, bm * 128, bcol0, 0, tid);
    const int NK = DM / 32;    // 64
    for (int it = 0; it < NK; it++) {
        if (it + 1 < NK) {
            gemm_load(Ah, Al, Bh, Bl, smg + ((it + 1) & 1) * 4 * GTS,
                      bm * 128, bcol0, (it + 1) * 32, tid);
            asm volatile("cp.async.wait_group 1;\n" ::);
        } else {
            asm volatile("cp.async.wait_group 0;\n" ::);
        }
        __syncthreads();
        bf16* s   = smg + (it & 1) * 4 * GTS;
        bf16* sAh = s;
        bf16* sAl = s + GTS;
        bf16* sBh = s + 2 * GTS;
        bf16* sBl = s + 3 * GTS;
        int l8 = lane & 15, brow = l8 & 7, bc8 = (l8 >> 3) << 3;
        #pragma unroll
        for (int k16 = 0; k16 < 2; k16++) {
            unsigned bh[4][2], bl[4][2];
            int bcol = k16 * 16 + bc8;
            #pragma unroll
            for (int nf = 0; nf < 4; nf++) {
                int n0 = wn * 32 + nf * 8;
                ldmx2(bh[nf], sptr(sBh + (n0 + brow) * GLD + bcol));
                ldmx2(bl[nf], sptr(sBl + (n0 + brow) * GLD + bcol));
            }
            int arow = wm * 64 + (lane & 15);
            int acol = k16 * 16 + ((lane >> 4) << 3);
            #pragma unroll
            for (int mf = 0; mf < 4; mf++) {
                unsigned ah[4], al[4];
                ldmx4(ah, sptr(sAh + (arow + mf * 16) * GLD + acol));
                ldmx4(al, sptr(sAl + (arow + mf * 16) * GLD + acol));
                #pragma unroll
                for (int nf = 0; nf < 4; nf++) {
                    mma_bf16(acc[mf][nf], ah, bh[nf]);
                    mma_bf16(acc[mf][nf], ah, bl[nf]);
                    mma_bf16(acc[mf][nf], al, bh[nf]);
                }
            }
        }
        __syncthreads();
    }

    if (mode) {
        // output projection: fp32 direct to extC
        #pragma unroll
        for (int mf = 0; mf < 4; mf++)
            #pragma unroll
            for (int nf = 0; nf < 4; nf++) {
                int row = bm * 128 + wm * 64 + mf * 16 + (lane >> 2);
                int col = bcol0 + wn * 32 + nf * 8 + ((lane & 3) << 1);
                *(float2*)(extC + (size_t)row * DM + col)       = make_float2(acc[mf][nf][0], acc[mf][nf][1]);
                *(float2*)(extC + (size_t)(row + 8) * DM + col) = make_float2(acc[mf][nf][2], acc[mf][nf][3]);
            }
        return;
    }

    // -------- fused QKV epilogue: acc -> smem -> RoPE(+scale) -> bf16 hi/lo --------
    float* st = (float*)smg;      // 128 x 132 fp32 tile (67584 B < 81920 B)
    #pragma unroll
    for (int mf = 0; mf < 4; mf++)
        #pragma unroll
        for (int nf = 0; nf < 4; nf++) {
            int r = wm * 64 + mf * 16 + (lane >> 2);
            int c = wn * 32 + nf * 8 + ((lane & 3) << 1);
            st[r * 132 + c]       = acc[mf][nf][0];
            st[r * 132 + c + 1]   = acc[mf][nf][1];
            st[(r + 8) * 132 + c]     = acc[mf][nf][2];
            st[(r + 8) * 132 + c + 1] = acc[mf][nf][3];
        }
    __syncthreads();

    int sel = bn >> 4;            // 0=Q 1=K 2=V
    int h   = bn & 15;
    #pragma unroll
    for (int i = 0; i < 32; i++) {
        int p = tid + 256 * i;    // 8192 (row,d) pairs
        int r = p >> 6, d = p & 63;
        float v0 = st[r * 132 + d];
        float v1 = st[r * 132 + d + 64];
        int row = bm * 128 + r;
        int s   = row & (SEQ - 1);
        int b   = row >> 11;
        size_t dst = (((size_t)b * NH + h) * SEQ + s) * HD;
        if (sel == 0) {
            float c = g_cos[s * 64 + d], sn = g_sin[s * 64 + d];
            wr_hilo(g_Qh, g_Ql, dst + d,      (v0 * c - v1 * sn) * SM_SCALE);
            wr_hilo(g_Qh, g_Ql, dst + d + 64, (v1 * c + v0 * sn) * SM_SCALE);
        } else if (sel == 1) {
            float c = g_cos[s * 64 + d], sn = g_sin[s * 64 + d];
            wr_hilo(g_Kh, g_Kl, dst + d,      v0 * c - v1 * sn);
            wr_hilo(g_Kh, g_Kl, dst + d + 64, v1 * c + v0 * sn);
        } else {
            wr_hilo(g_Vh, g_Vl, dst + d,      v0);
            wr_hilo(g_Vh, g_Vl, dst + d + 64, v1);
        }
    }
}

// ---------------- flash attention (compensated, double-buffered KV) ----------------
#define ALD  136
#define SSTG (4*64*ALD)     // one KV stage (elements): Kh|Kl|Vh|Vl
#define ATT_SMEM ((size_t)(2*128*ALD + 2*SSTG) * sizeof(bf16))   // 208896 B

__global__ void __launch_bounds__(256,1) attn_kernel()
{
    extern __shared__ bf16 sma[];
    bf16* sQh = sma;
    bf16* sQl = sQh + 128 * ALD;
    bf16* stg0 = sQl + 128 * ALD;

    int tid = threadIdx.x, lane = tid & 31, w = tid >> 5;
    int qt = blockIdx.x, h = blockIdx.y, b = blockIdx.z;
    int qb = qt * 128;
    size_t base = (((size_t)b * NH + h) * SEQ) * HD;
    int nkv = 2 * qt + 2;

    // Q (group 1)
    for (int c = tid; c < 2048; c += 256) {
        int r = c >> 4, c8 = (c & 15) << 3;
        size_t g = base + (size_t)(qb + r) * HD + c8;
        cpa16(sptr(sQh + r * ALD + c8), g_Qh + g);
        cpa16(sptr(sQl + r * ALD + c8), g_Ql + g);
    }
    asm volatile("cp.async.commit_group;\n" ::);

    auto load_kv = [&](int it, int st) {
        bf16* sb = stg0 + st * SSTG;
        int kb = it * 64;
        for (int c = tid; c < 1024; c += 256) {
            int r = c >> 4, c8 = (c & 15) << 3;
            size_t g = base + (size_t)(kb + r) * HD + c8;
            unsigned d = sptr(sb + r * ALD + c8);
            cpa16(d,                        g_Kh + g);
            cpa16(d + 2 * 64 * ALD,         g_Kl + g);
            cpa16(d + 4 * 64 * ALD,         g_Vh + g);
            cpa16(d + 6 * 64 * ALD,         g_Vl + g);
        }
        asm volatile("cp.async.commit_group;\n" ::);
    };

    load_kv(0, 0);
    load_kv(1, 1);

    float o[16][4];
    #pragma unroll
    for (int i = 0; i < 16; i++) { o[i][0]=0.f; o[i][1]=0.f; o[i][2]=0.f; o[i][3]=0.f; }
    float m0 = -1e30f, m1 = -1e30f, l0 = 0.f, l1 = 0.f;

    for (int it = 0; it < nkv; it++) {
        int kb = it * 64;
        if (it == nkv - 1) { asm volatile("cp.async.wait_group 0;\n" ::); }
        else               { asm volatile("cp.async.wait_group 1;\n" ::); }
        __syncthreads();
        bf16* sb  = stg0 + (it & 1) * SSTG;
        bf16* sKh = sb;
        bf16* sKl = sb + 64 * ALD;
        bf16* sVh = sb + 128 * ALD;
        bf16* sVl = sb + 192 * ALD;

        // scores: S = Q K^T (compensated)
        float sc[8][4];
        #pragma unroll
        for (int i = 0; i < 8; i++) { sc[i][0]=0.f; sc[i][1]=0.f; sc[i][2]=0.f; sc[i][3]=0.f; }
        int arow = w * 16 + (lane & 15);
        int l8 = lane & 15, brow = l8 & 7, bc8 = (l8 >> 3) << 3;
        #pragma unroll
        for (int k16 = 0; k16 < 8; k16++) {
            unsigned ah[4], al[4];
            int acol = k16 * 16 + ((lane >> 4) << 3);
            ldmx4(ah, sptr(sQh + arow * ALD + acol));
            ldmx4(al, sptr(sQl + arow * ALD + acol));
            #pragma unroll
            for (int nf = 0; nf < 8; nf++) {
                unsigned bh[2], bl[2];
                ldmx2(bh, sptr(sKh + (nf * 8 + brow) * ALD + k16 * 16 + bc8));
                ldmx2(bl, sptr(sKl + (nf * 8 + brow) * ALD + k16 * 16 + bc8));
                mma_bf16(sc[nf], ah, bh);
                mma_bf16(sc[nf], ah, bl);
                mma_bf16(sc[nf], al, bh);
            }
        }
        // causal mask (last 2 kv tiles straddle the diagonal)
        int qr0 = qb + w * 16 + (lane >> 2);
        if (it >= nkv - 2) {
            #pragma unroll
            for (int nf = 0; nf < 8; nf++) {
                int col = kb + nf * 8 + ((lane & 3) << 1);
                if (col     > qr0)     sc[nf][0] = -1e30f;
                if (col + 1 > qr0)     sc[nf][1] = -1e30f;
                if (col     > qr0 + 8) sc[nf][2] = -1e30f;
                if (col + 1 > qr0 + 8) sc[nf][3] = -1e30f;
            }
        }
        // online softmax
        float mx0 = -1e30f, mx1 = -1e30f;
        #pragma unroll
        for (int nf = 0; nf < 8; nf++) {
            mx0 = fmaxf(mx0, fmaxf(sc[nf][0], sc[nf][1]));
            mx1 = fmaxf(mx1, fmaxf(sc[nf][2], sc[nf][3]));
        }
        mx0 = fmaxf(mx0, __shfl_xor_sync(0xffffffffu, mx0, 1));
        mx0 = fmaxf(mx0, __shfl_xor_sync(0xffffffffu, mx0, 2));
        mx1 = fmaxf(mx1, __shfl_xor_sync(0xffffffffu, mx1, 1));
        mx1 = fmaxf(mx1, __shfl_xor_sync(0xffffffffu, mx1, 2));
        float mn0 = fmaxf(m0, mx0), mn1 = fmaxf(m1, mx1);
        float a0 = __expf(m0 - mn0), a1 = __expf(m1 - mn1);
        float s0 = 0.f, s1 = 0.f;
        #pragma unroll
        for (int nf = 0; nf < 8; nf++) {
            sc[nf][0] = __expf(sc[nf][0] - mn0);
            sc[nf][1] = __expf(sc[nf][1] - mn0);
            sc[nf][2] = __expf(sc[nf][2] - mn1);
            sc[nf][3] = __expf(sc[nf][3] - mn1);
            s0 += sc[nf][0] + sc[nf][1];
            s1 += sc[nf][2] + sc[nf][3];
        }
        s0 += __shfl_xor_sync(0xffffffffu, s0, 1);
        s0 += __shfl_xor_sync(0xffffffffu, s0, 2);
        s1 += __shfl_xor_sync(0xffffffffu, s1, 1);
        s1 += __shfl_xor_sync(0xffffffffu, s1, 2);
        l0 = a0 * l0 + s0;
        l1 = a1 * l1 + s1;
        m0 = mn0; m1 = mn1;
        #pragma unroll
        for (int i = 0; i < 16; i++) { o[i][0]*=a0; o[i][1]*=a0; o[i][2]*=a1; o[i][3]*=a1; }

        // PV (compensated): P C-frags become A-frags directly
        #pragma unroll
        for (int k16 = 0; k16 < 4; k16++) {
            unsigned ph[4], pl[4];
            split2(sc[2*k16][0],   sc[2*k16][1],   ph[0], pl[0]);
            split2(sc[2*k16][2],   sc[2*k16][3],   ph[1], pl[1]);
            split2(sc[2*k16+1][0], sc[2*k16+1][1], ph[2], pl[2]);
            split2(sc[2*k16+1][2], sc[2*k16+1][3], ph[3], pl[3]);
            #pragma unroll
            for (int nf = 0; nf < 16; nf++) {
                unsigned vh[2], vl[2];
                ldmx2t(vh, sptr(sVh + (k16 * 16 + l8) * ALD + nf * 8));
                ldmx2t(vl, sptr(sVl + (k16 * 16 + l8) * ALD + nf * 8));
                mma_bf16(o[nf], ph, vh);
                mma_bf16(o[nf], ph, vl);
                mma_bf16(o[nf], pl, vh);
            }
        }
        __syncthreads();
        if (it + 2 < nkv) load_kv(it + 2, it & 1);
    }
    // epilogue: O /= l, write bf16 hi/lo AO directly into g_Xh/g_Xl, [B,S,H*HD]
    float r0 = 1.f / l0, r1 = 1.f / l1;
    int srow = qb + w * 16 + (lane >> 2);
    #pragma unroll
    for (int nf = 0; nf < 16; nf++) {
        int col = nf * 8 + ((lane & 3) << 1);
        size_t p0 = (((size_t)b * SEQ + srow) * NH + h) * HD + col;
        size_t p1 = (((size_t)b * SEQ + srow + 8) * NH + h) * HD + col;
        unsigned hh, ll;
        split2(o[nf][0] * r0, o[nf][1] * r0, hh, ll);
        *(unsigned*)(g_Xh + p0) = hh; *(unsigned*)(g_Xl + p0) = ll;
        split2(o[nf][2] * r1, o[nf][3] * r1, hh, ll);
        *(unsigned*)(g_Xh + p1) = hh; *(unsigned*)(g_Xl + p1) = ll;
    }
}

// ---------------- launch ----------------
extern "C" void kernel_launch(void* const* d_in, const int* in_sizes, int n_in,
                              void* d_out, int out_size)
{
    const float* X = (const float*)d_in[0];
    float* out = (float*)d_out;

    cudaFuncSetAttribute(gemm_kernel, cudaFuncAttributeMaxDynamicSharedMemorySize, (int)GSMEM);
    cudaFuncSetAttribute(attn_kernel, cudaFuncAttributeMaxDynamicSharedMemorySize, (int)ATT_SMEM);

    int n4x = (int)(MD / 4);
    split_kernel<<<(n4x + 255) / 256, 256>>>(X, 0, 0, n4x);
    int n4w = (int)(DD / 4);
    for (int i = 0; i < 4; i++)
        split_kernel<<<(n4w + 255) / 256, 256>>>((const float*)d_in[1 + i], 1, (size_t)i * DD, n4w);
    rope_table_kernel<<<(SEQ * 64) / 256, 256>>>();

    // fused QKV projections + RoPE + relayout + hi/lo split
    gemm_kernel<<<dim3(48, MR / 128), 256, GSMEM>>>(out, 0);

    // causal flash attention -> AO (hi/lo) in g_Xh/g_Xl
    attn_kernel<<<dim3(SEQ / 128, NH, BATCH), 256, ATT_SMEM>>>();

    // output projection
    gemm_kernel<<<dim3(16, MR / 128), 256, GSMEM>>>(out, 1);
}

// round 13
// speedup vs baseline: 1.4630x; 1.2329x over previous
#include <cuda_runtime.h>
#include <cuda_bf16.h>
#include <cmath>

typedef __nv_bfloat16 bf16;

#define BATCH 2
#define SEQ   2048
#define DM    2048
#define NH    16
#define HD    128
#define MR    (BATCH*SEQ)
#define MD    ((size_t)MR*DM)
#define DD    ((size_t)DM*DM)
#define SM_SCALE 0.08838834764831845f

// ---------------- static device scratch ----------------
__device__ __align__(1024) bf16 g_Xh[MD], g_Xl[MD];
__device__ __align__(1024) bf16 g_Wh[4*DD], g_Wl[4*DD];
__device__ __align__(1024) bf16 g_Qh[MD], g_Ql[MD], g_Kh[MD], g_Kl[MD], g_Vh[MD], g_Vl[MD];
__device__ float g_cos[SEQ*64], g_sin[SEQ*64];

// ---------------- helpers ----------------
__device__ __forceinline__ unsigned sptr(const void* p) {
    return (unsigned)__cvta_generic_to_shared(p);
}
__device__ __forceinline__ void ldmx4(unsigned* r, unsigned a) {
    asm volatile("ldmatrix.sync.aligned.m8n8.x4.shared.b16 {%0,%1,%2,%3}, [%4];\n"
        : "=r"(r[0]), "=r"(r[1]), "=r"(r[2]), "=r"(r[3]) : "r"(a));
}
__device__ __forceinline__ void ldmx4t(unsigned* r, unsigned a) {
    asm volatile("ldmatrix.sync.aligned.m8n8.x4.trans.shared.b16 {%0,%1,%2,%3}, [%4];\n"
        : "=r"(r[0]), "=r"(r[1]), "=r"(r[2]), "=r"(r[3]) : "r"(a));
}
__device__ __forceinline__ void mma_bf16(float* c, const unsigned* a, const unsigned* b) {
    asm volatile("mma.sync.aligned.m16n8k16.row.col.f32.bf16.bf16.f32 "
        "{%0,%1,%2,%3}, {%4,%5,%6,%7}, {%8,%9}, {%0,%1,%2,%3};\n"
        : "+f"(c[0]), "+f"(c[1]), "+f"(c[2]), "+f"(c[3])
        : "r"(a[0]), "r"(a[1]), "r"(a[2]), "r"(a[3]), "r"(b[0]), "r"(b[1]));
}
__device__ __forceinline__ void cpa16(unsigned s, const void* g) {
    asm volatile("cp.async.cg.shared.global [%0], [%1], 16;\n" :: "r"(s), "l"(g));
}
__device__ __forceinline__ void split2(float x, float y, unsigned& hi, unsigned& lo) {
    bf16 hx = __float2bfloat16(x);
    bf16 hy = __float2bfloat16(y);
    bf16 lx = __float2bfloat16(x - __bfloat162float(hx));
    bf16 ly = __float2bfloat16(y - __bfloat162float(hy));
    hi = (unsigned)__bfloat16_as_ushort(hx) | ((unsigned)__bfloat16_as_ushort(hy) << 16);
    lo = (unsigned)__bfloat16_as_ushort(lx) | ((unsigned)__bfloat16_as_ushort(ly) << 16);
}
__device__ __forceinline__ void wr_hilo(bf16* H, bf16* L, size_t i, float x) {
    bf16 h = __float2bfloat16(x);
    H[i] = h;
    L[i] = __float2bfloat16(x - __bfloat162float(h));
}

// ---------------- fused prep: X split + W splits + RoPE table ----------------
__global__ void prep_kernel(const float* __restrict__ X,
                            const float* __restrict__ W0, const float* __restrict__ W1,
                            const float* __restrict__ W2, const float* __restrict__ W3)
{
    size_t i = (size_t)blockIdx.x * blockDim.x + threadIdx.x;
    const size_t N1 = MD / 4;          // X float4 quads
    const size_t N2 = N1 + DD;         // + all-W float4 quads (4 * DD/4)
    if (i < N1) {
        float4 v = ((const float4*)X)[i];
        unsigned h0, l0, h1, l1;
        split2(v.x, v.y, h0, l0);
        split2(v.z, v.w, h1, l1);
        ((uint2*)g_Xh)[i] = make_uint2(h0, h1);
        ((uint2*)g_Xl)[i] = make_uint2(l0, l1);
    } else if (i < N2) {
        size_t j = i - N1;
        int w = (int)(j >> 20);                 // DD/4 = 2^20
        size_t k = j & ((DD / 4) - 1);
        const float* W = (w == 0) ? W0 : (w == 1) ? W1 : (w == 2) ? W2 : W3;
        float4 v = ((const float4*)W)[k];
        unsigned h0, l0, h1, l1;
        split2(v.x, v.y, h0, l0);
        split2(v.z, v.w, h1, l1);
        ((uint2*)g_Wh)[j] = make_uint2(h0, h1);
        ((uint2*)g_Wl)[j] = make_uint2(l0, l1);
    } else {
        int t = (int)(i - N2);
        if (t < SEQ * 64) {
            int j = t & 63, s = t >> 6;
            float invf = (float)exp(-(double)j * (9.210340371976184 / 64.0));
            float ang = (float)s * invf;    // mimic reference fp32 t*inv_freq rounding
            g_cos[t] = (float)cos((double)ang);
            g_sin[t] = (float)sin((double)ang);
        }
    }
}

// ======== compensated bf16 GEMM: C[M,N] = A[M,K] * B[N,K]^T (legacy mma) ========
// tile 128x128, K-chunk 32, 3-stage cp.async ring (one sync/iter), occ 2.
// SMEM layout: 64B logical rows packed 2-per-128B row with SW128-style swizzle.
#define QS    8192u          // quadrant bytes (128 rows x 64B)
#define STB   (4u*QS)        // stage bytes: Ah|Al|Bh|Bl = 32768
#define GSMEM ((size_t)3*STB)  // 98304 B

__device__ __forceinline__ unsigned qoff(int r, int ce) {
    unsigned b = ((unsigned)(r >> 1) << 7) | ((unsigned)(r & 1) << 6) | ((unsigned)ce << 1);
    return b ^ ((b >> 3) & 0x70);
}

__global__ void __launch_bounds__(256,2) gemm_kernel(float* extC, int mode)
{
    extern __shared__ __align__(1024) char smg[];
    unsigned sb = sptr(smg);
    int tid = threadIdx.x, lane = tid & 31, wid = tid >> 5;
    int wm = wid & 1, wn = wid >> 1;
    int bm = blockIdx.y, bn = blockIdx.x;

    int w_idx = mode ? 3 : (bn >> 4);
    int bcol0 = mode ? bn * 128 : (bn & 15) * 128;
    const bf16* Ah = g_Xh;
    const bf16* Al = g_Xl;
    const bf16* Bh = g_Wh + (size_t)w_idx * DD;
    const bf16* Bl = g_Wl + (size_t)w_idx * DD;

    auto load_st = [&](int kt, int st) {
        unsigned base = sb + (unsigned)st * STB;
        int k0 = kt * 32;
        #pragma unroll
        for (int j = 0; j < 2; j++) {
            int cid = tid + 256 * j;
            int r = cid >> 2, ce = (cid & 3) << 3;
            unsigned off = qoff(r, ce);
            size_t ga = (size_t)(bm * 128 + r) * DM + k0 + ce;
            size_t gb = (size_t)(bcol0 + r) * DM + k0 + ce;
            cpa16(base + off,          Ah + ga);
            cpa16(base + QS + off,     Al + ga);
            cpa16(base + 2*QS + off,   Bh + gb);
            cpa16(base + 3*QS + off,   Bl + gb);
        }
        asm volatile("cp.async.commit_group;\n" ::);
    };

    float acc[4][4][4];
    #pragma unroll
    for (int a = 0; a < 4; a++)
        #pragma unroll
        for (int b = 0; b < 4; b++)
            { acc[a][b][0]=0.f; acc[a][b][1]=0.f; acc[a][b][2]=0.f; acc[a][b][3]=0.f; }

    const int NK = DM / 32;    // 64
    load_st(0, 0);
    load_st(1, 1);

    // per-lane fragment coordinates
    int arB = wm * 64 + (lane & 15);          // A row (plus mf*16)
    int acB = (lane >> 4) << 3;               // A col base (plus k16*16)
    int brB = wn * 32 + (lane & 7) + ((lane >> 4) << 3);   // B pair row (plus p*16)
    int bcB = ((lane >> 3) & 1) << 3;                      // B pair col (plus k16*16)

    for (int it = 0; it < NK; it++) {
        int st = it % 3;
        if (it == NK - 1) { asm volatile("cp.async.wait_group 0;\n" ::); }
        else              { asm volatile("cp.async.wait_group 1;\n" ::); }
        __syncthreads();
        unsigned sA = sb + (unsigned)st * STB;
        #pragma unroll
        for (int k16 = 0; k16 < 2; k16++) {
            int kc = k16 * 16;
            unsigned bhp[2][4], blp[2][4];
            #pragma unroll
            for (int p = 0; p < 2; p++) {
                unsigned off = qoff(brB + p * 16, kc + bcB);
                ldmx4(bhp[p], sA + 2*QS + off);
                ldmx4(blp[p], sA + 3*QS + off);
            }
            #pragma unroll
            for (int mf = 0; mf < 4; mf++) {
                unsigned ah[4], al[4];
                unsigned off = qoff(arB + mf * 16, kc + acB);
                ldmx4(ah, sA + off);
                ldmx4(al, sA + QS + off);
                #pragma unroll
                for (int nf = 0; nf < 4; nf++) {
                    const unsigned* b2h = &bhp[nf >> 1][(nf & 1) * 2];
                    const unsigned* b2l = &blp[nf >> 1][(nf & 1) * 2];
                    mma_bf16(acc[mf][nf], ah, b2h);
                    mma_bf16(acc[mf][nf], ah, b2l);
                    mma_bf16(acc[mf][nf], al, b2h);
                }
            }
        }
        if (it + 2 < NK) load_st(it + 2, (it + 2) % 3);
    }

    if (mode) {
        // output projection: fp32 direct to extC
        #pragma unroll
        for (int mf = 0; mf < 4; mf++)
            #pragma unroll
            for (int nf = 0; nf < 4; nf++) {
                int row = bm * 128 + wm * 64 + mf * 16 + (lane >> 2);
                int col = bcol0 + wn * 32 + nf * 8 + ((lane & 3) << 1);
                *(float2*)(extC + (size_t)row * DM + col)       = make_float2(acc[mf][nf][0], acc[mf][nf][1]);
                *(float2*)(extC + (size_t)(row + 8) * DM + col) = make_float2(acc[mf][nf][2], acc[mf][nf][3]);
            }
        return;
    }

    // -------- fused QKV epilogue: acc -> smem -> RoPE(+scale) -> bf16 hi/lo --------
    __syncthreads();               // all stages idle; reuse smem as fp32 tile
    float* stf = (float*)smg;      // 128 x 132 fp32 (67584 B < 98304 B)
    #pragma unroll
    for (int mf = 0; mf < 4; mf++)
        #pragma unroll
        for (int nf = 0; nf < 4; nf++) {
            int r = wm * 64 + mf * 16 + (lane >> 2);
            int c = wn * 32 + nf * 8 + ((lane & 3) << 1);
            stf[r * 132 + c]           = acc[mf][nf][0];
            stf[r * 132 + c + 1]       = acc[mf][nf][1];
            stf[(r + 8) * 132 + c]     = acc[mf][nf][2];
            stf[(r + 8) * 132 + c + 1] = acc[mf][nf][3];
        }
    __syncthreads();

    int sel = bn >> 4;            // 0=Q 1=K 2=V
    int h   = bn & 15;
    #pragma unroll
    for (int i = 0; i < 32; i++) {
        int p = tid + 256 * i;    // 8192 (row,d) pairs
        int r = p >> 6, d = p & 63;
        float v0 = stf[r * 132 + d];
        float v1 = stf[r * 132 + d + 64];
        int row = bm * 128 + r;
        int s   = row & (SEQ - 1);
        int b   = row >> 11;
        size_t dst = (((size_t)b * NH + h) * SEQ + s) * HD;
        if (sel == 0) {
            float c = g_cos[s * 64 + d], sn = g_sin[s * 64 + d];
            wr_hilo(g_Qh, g_Ql, dst + d,      (v0 * c - v1 * sn) * SM_SCALE);
            wr_hilo(g_Qh, g_Ql, dst + d + 64, (v1 * c + v0 * sn) * SM_SCALE);
        } else if (sel == 1) {
            float c = g_cos[s * 64 + d], sn = g_sin[s * 64 + d];
            wr_hilo(g_Kh, g_Kl, dst + d,      v0 * c - v1 * sn);
            wr_hilo(g_Kh, g_Kl, dst + d + 64, v1 * c + v0 * sn);
        } else {
            wr_hilo(g_Vh, g_Vl, dst + d,      v0);
            wr_hilo(g_Vh, g_Vl, dst + d + 64, v1);
        }
    }
}

// ---------------- flash attention (compensated, double-buffered KV) ----------------
#define ALD  136
#define SSTG (4*64*ALD)     // one KV stage (elements): Kh|Kl|Vh|Vl
#define ATT_SMEM ((size_t)(2*128*ALD + 2*SSTG) * sizeof(bf16))   // 208896 B

__global__ void __launch_bounds__(256,1) attn_kernel()
{
    extern __shared__ bf16 sma[];
    bf16* sQh = sma;
    bf16* sQl = sQh + 128 * ALD;
    bf16* stg0 = sQl + 128 * ALD;

    int tid = threadIdx.x, lane = tid & 31, w = tid >> 5;
    int qt = (int)(gridDim.x - 1 - blockIdx.x);   // heavy tiles first
    int h = blockIdx.y, b = blockIdx.z;
    int qb = qt * 128;
    size_t base = (((size_t)b * NH + h) * SEQ) * HD;
    int nkv = 2 * qt + 2;

    for (int c = tid; c < 2048; c += 256) {
        int r = c >> 4, c8 = (c & 15) << 3;
        size_t g = base + (size_t)(qb + r) * HD + c8;
        cpa16(sptr(sQh + r * ALD + c8), g_Qh + g);
        cpa16(sptr(sQl + r * ALD + c8), g_Ql + g);
    }
    asm volatile("cp.async.commit_group;\n" ::);

    auto load_kv = [&](int it, int st) {
        bf16* sbk = stg0 + st * SSTG;
        int kb = it * 64;
        for (int c = tid; c < 1024; c += 256) {
            int r = c >> 4, c8 = (c & 15) << 3;
            size_t g = base + (size_t)(kb + r) * HD + c8;
            unsigned d = sptr(sbk + r * ALD + c8);
            cpa16(d,                g_Kh + g);
            cpa16(d + 2*64*ALD,     g_Kl + g);
            cpa16(d + 4*64*ALD,     g_Vh + g);
            cpa16(d + 6*64*ALD,     g_Vl + g);
        }
        asm volatile("cp.async.commit_group;\n" ::);
    };

    load_kv(0, 0);
    load_kv(1, 1);

    float o[16][4];
    #pragma unroll
    for (int i = 0; i < 16; i++) { o[i][0]=0.f; o[i][1]=0.f; o[i][2]=0.f; o[i][3]=0.f; }
    float m0 = -1e30f, m1 = -1e30f, l0 = 0.f, l1 = 0.f;

    // per-lane pair-load coordinates
    int arow = w * 16 + (lane & 15);
    int acol0 = (lane >> 4) << 3;
    int brow2 = (lane & 7) + ((lane >> 4) << 3);
    int bc2   = ((lane >> 3) & 1) << 3;

    for (int it = 0; it < nkv; it++) {
        int kb = it * 64;
        if (it == nkv - 1) { asm volatile("cp.async.wait_group 0;\n" ::); }
        else               { asm volatile("cp.async.wait_group 1;\n" ::); }
        __syncthreads();
        bf16* sbk = stg0 + (it & 1) * SSTG;
        bf16* sKh = sbk;
        bf16* sKl = sbk + 64 * ALD;
        bf16* sVh = sbk + 128 * ALD;
        bf16* sVl = sbk + 192 * ALD;

        // scores: S = Q K^T (compensated)
        float sc[8][4];
        #pragma unroll
        for (int i = 0; i < 8; i++) { sc[i][0]=0.f; sc[i][1]=0.f; sc[i][2]=0.f; sc[i][3]=0.f; }
        #pragma unroll
        for (int k16 = 0; k16 < 8; k16++) {
            unsigned ah[4], al[4];
            int acol = k16 * 16 + acol0;
            ldmx4(ah, sptr(sQh + arow * ALD + acol));
            ldmx4(al, sptr(sQl + arow * ALD + acol));
            #pragma unroll
            for (int p = 0; p < 4; p++) {
                unsigned bhp[4], blp[4];
                unsigned ad = sptr(sKh + (p * 16 + brow2) * ALD + k16 * 16 + bc2);
                ldmx4(bhp, ad);
                ldmx4(blp, ad + 2 * 64 * ALD);   // sKl at +64*ALD elements = +128*ALD bytes
                mma_bf16(sc[2*p],   ah, &bhp[0]);
                mma_bf16(sc[2*p],   ah, &blp[0]);
                mma_bf16(sc[2*p],   al, &bhp[0]);
                mma_bf16(sc[2*p+1], ah, &bhp[2]);
                mma_bf16(sc[2*p+1], ah, &blp[2]);
                mma_bf16(sc[2*p+1], al, &bhp[2]);
            }
        }
        // causal mask (last 2 kv tiles straddle the diagonal)
        int qr0 = qb + w * 16 + (lane >> 2);
        if (it >= nkv - 2) {
            #pragma unroll
            for (int nf = 0; nf < 8; nf++) {
                int col = kb + nf * 8 + ((lane & 3) << 1);
                if (col     > qr0)     sc[nf][0] = -1e30f;
                if (col + 1 > qr0)     sc[nf][1] = -1e30f;
                if (col     > qr0 + 8) sc[nf][2] = -1e30f;
                if (col + 1 > qr0 + 8) sc[nf][3] = -1e30f;
            }
        }
        // online softmax
        float mx0 = -1e30f, mx1 = -1e30f;
        #pragma unroll
        for (int nf = 0; nf < 8; nf++) {
            mx0 = fmaxf(mx0, fmaxf(sc[nf][0], sc[nf][1]));
            mx1 = fmaxf(mx1, fmaxf(sc[nf][2], sc[nf][3]));
        }
        mx0 = fmaxf(mx0, __shfl_xor_sync(0xffffffffu, mx0, 1));
        mx0 = fmaxf(mx0, __shfl_xor_sync(0xffffffffu, mx0, 2));
        mx1 = fmaxf(mx1, __shfl_xor_sync(0xffffffffu, mx1, 1));
        mx1 = fmaxf(mx1, __shfl_xor_sync(0xffffffffu, mx1, 2));
        float mn0 = fmaxf(m0, mx0), mn1 = fmaxf(m1, mx1);
        float a0 = __expf(m0 - mn0), a1 = __expf(m1 - mn1);
        float s0 = 0.f, s1 = 0.f;
        #pragma unroll
        for (int nf = 0; nf < 8; nf++) {
            sc[nf][0] = __expf(sc[nf][0] - mn0);
            sc[nf][1] = __expf(sc[nf][1] - mn0);
            sc[nf][2] = __expf(sc[nf][2] - mn1);
            sc[nf][3] = __expf(sc[nf][3] - mn1);
            s0 += sc[nf][0] + sc[nf][1];
            s1 += sc[nf][2] + sc[nf][3];
        }
        s0 += __shfl_xor_sync(0xffffffffu, s0, 1);
        s0 += __shfl_xor_sync(0xffffffffu, s0, 2);
        s1 += __shfl_xor_sync(0xffffffffu, s1, 1);
        s1 += __shfl_xor_sync(0xffffffffu, s1, 2);
        l0 = a0 * l0 + s0;
        l1 = a1 * l1 + s1;
        m0 = mn0; m1 = mn1;
        #pragma unroll
        for (int i = 0; i < 16; i++) { o[i][0]*=a0; o[i][1]*=a0; o[i][2]*=a1; o[i][3]*=a1; }

        // PV (compensated): P C-frags become A-frags directly; V via x4.trans pairs
        int vrB = (lane & 7) + (((lane >> 3) & 1) << 3);
        int vcB = (lane >> 4) << 3;
        #pragma unroll
        for (int k16 = 0; k16 < 4; k16++) {
            unsigned ph[4], pl[4];
            split2(sc[2*k16][0],   sc[2*k16][1],   ph[0], pl[0]);
            split2(sc[2*k16][2],   sc[2*k16][3],   ph[1], pl[1]);
            split2(sc[2*k16+1][0], sc[2*k16+1][1], ph[2], pl[2]);
            split2(sc[2*k16+1][2], sc[2*k16+1][3], ph[3], pl[3]);
            #pragma unroll
            for (int p = 0; p < 8; p++) {
                unsigned vhp[4], vlp[4];
                unsigned ad = sptr(sVh + (k16 * 16 + vrB) * ALD + p * 16 + vcB);
                ldmx4t(vhp, ad);
                ldmx4t(vlp, ad + 2 * 64 * ALD);   // sVl at +64*ALD elements
                mma_bf16(o[2*p],   ph, &vhp[0]);
                mma_bf16(o[2*p],   ph, &vlp[0]);
                mma_bf16(o[2*p],   pl, &vhp[0]);
                mma_bf16(o[2*p+1], ph, &vhp[2]);
                mma_bf16(o[2*p+1], ph, &vlp[2]);
                mma_bf16(o[2*p+1], pl, &vhp[2]);
            }
        }
        __syncthreads();
        if (it + 2 < nkv) load_kv(it + 2, it & 1);
    }
    // epilogue: O /= l, write bf16 hi/lo AO directly into g_Xh/g_Xl, [B,S,H*HD]
    float r0 = 1.f / l0, r1 = 1.f / l1;
    int srow = qb + w * 16 + (lane >> 2);
    #pragma unroll
    for (int nf = 0; nf < 16; nf++) {
        int col = nf * 8 + ((lane & 3) << 1);
        size_t p0 = (((size_t)b * SEQ + srow) * NH + h) * HD + col;
        size_t p1 = (((size_t)b * SEQ + srow + 8) * NH + h) * HD + col;
        unsigned hh, ll;
        split2(o[nf][0] * r0, o[nf][1] * r0, hh, ll);
        *(unsigned*)(g_Xh + p0) = hh; *(unsigned*)(g_Xl + p0) = ll;
        split2(o[nf][2] * r1, o[nf][3] * r1, hh, ll);
        *(unsigned*)(g_Xh + p1) = hh; *(unsigned*)(g_Xl + p1) = ll;
    }
}

// ---------------- launch ----------------
extern "C" void kernel_launch(void* const* d_in, const int* in_sizes, int n_in,
                              void* d_out, int out_size)
{
    const float* X = (const float*)d_in[0];
    float* out = (float*)d_out;

    cudaFuncSetAttribute(gemm_kernel, cudaFuncAttributeMaxDynamicSharedMemorySize, (int)GSMEM);
    cudaFuncSetAttribute(attn_kernel, cudaFuncAttributeMaxDynamicSharedMemorySize, (int)ATT_SMEM);

    // fused prep: X split, 4 W splits, RoPE table  (25088 blocks)
    size_t total = MD / 4 + DD + (size_t)SEQ * 64;
    prep_kernel<<<(unsigned)((total + 255) / 256), 256>>>(
        X, (const float*)d_in[1], (const float*)d_in[2],
        (const float*)d_in[3], (const float*)d_in[4]);

    // fused QKV projections + RoPE + relayout + hi/lo split
    gemm_kernel<<<dim3(48, MR / 128), 256, GSMEM>>>(out, 0);

    // causal flash attention -> AO (hi/lo) in g_Xh/g_Xl
    attn_kernel<<<dim3(SEQ / 128, NH, BATCH), 256, ATT_SMEM>>>();

    // output projection
    gemm_kernel<<<dim3(16, MR / 128), 256, GSMEM>>>(out, 1);
}